// round 3
// baseline (speedup 1.0000x reference)
#include <cuda_runtime.h>
#include <math.h>

// Problem constants (fixed shapes)
#define HSZ   2048
#define NH    16
#define NKV   4
#define HD    128
#define BATCH 2
#define SEQ   2048
#define NTOK  (BATCH*SEQ)          // 4096

// Scratch (device globals; allocation is forbidden)
__device__ float g_q[(size_t)NTOK*NH*HD];     // 33.5 MB
__device__ float g_k[(size_t)NTOK*NKV*HD];    //  8.4 MB
__device__ float g_v[(size_t)NTOK*NKV*HD];    //  8.4 MB
__device__ float g_attn[(size_t)NTOK*NH*HD];  // 33.5 MB

// ---------------------------------------------------------------------------
// Tiled SGEMM: C[M,N] = A[M,K] @ B[K,N], row-major, fp32.
// BM=64, BN=64, BK=16, 128 threads, 4x8 micro-tile per thread.
// ---------------------------------------------------------------------------
__global__ void __launch_bounds__(128) sgemm_kernel(
    const float* __restrict__ A, const float* __restrict__ Bw,
    float* __restrict__ C, int M, int N, int K)
{
    __shared__ float sA[64 * 17];   // [m][k], pad 17 to dodge conflicts
    __shared__ float sB[16 * 64];   // [k][n]

    const int tid = threadIdx.x;
    const int ty  = tid >> 3;       // 0..15 -> rows ty*4..ty*4+3
    const int tx  = tid & 7;        // 0..7  -> cols tx*8..tx*8+7
    const int m0  = blockIdx.y * 64;
    const int n0  = blockIdx.x * 64;

    float acc[4][8];
#pragma unroll
    for (int i = 0; i < 4; i++)
#pragma unroll
        for (int j = 0; j < 8; j++) acc[i][j] = 0.0f;

    for (int k0 = 0; k0 < K; k0 += 16) {
        // Load A tile 64x16 (256 float4, 2 per thread)
#pragma unroll
        for (int i = 0; i < 2; i++) {
            int e  = i * 128 + tid;         // float4 index
            int m  = e >> 2;
            int kc = (e & 3) * 4;
            float4 va = *(const float4*)&A[(size_t)(m0 + m) * K + k0 + kc];
            sA[m * 17 + kc + 0] = va.x;
            sA[m * 17 + kc + 1] = va.y;
            sA[m * 17 + kc + 2] = va.z;
            sA[m * 17 + kc + 3] = va.w;
        }
        // Load B tile 16x64 (256 float4, 2 per thread)
#pragma unroll
        for (int i = 0; i < 2; i++) {
            int e = i * 128 + tid;
            int r = e >> 4;
            int c = (e & 15) * 4;
            *(float4*)&sB[r * 64 + c] =
                *(const float4*)&Bw[(size_t)(k0 + r) * N + n0 + c];
        }
        __syncthreads();

#pragma unroll
        for (int kk = 0; kk < 16; kk++) {
            float a[4];
#pragma unroll
            for (int i = 0; i < 4; i++) a[i] = sA[(ty * 4 + i) * 17 + kk];
            float4 b0 = *(const float4*)&sB[kk * 64 + tx * 8];
            float4 b1 = *(const float4*)&sB[kk * 64 + tx * 8 + 4];
            float b[8] = {b0.x, b0.y, b0.z, b0.w, b1.x, b1.y, b1.z, b1.w};
#pragma unroll
            for (int i = 0; i < 4; i++)
#pragma unroll
                for (int j = 0; j < 8; j++)
                    acc[i][j] += a[i] * b[j];
        }
        __syncthreads();
    }

#pragma unroll
    for (int i = 0; i < 4; i++) {
        float4 o0 = {acc[i][0], acc[i][1], acc[i][2], acc[i][3]};
        float4 o1 = {acc[i][4], acc[i][5], acc[i][6], acc[i][7]};
        size_t row = (size_t)(m0 + ty * 4 + i) * N + n0 + tx * 8;
        *(float4*)&C[row]     = o0;
        *(float4*)&C[row + 4] = o1;
    }
}

// ---------------------------------------------------------------------------
// RoPE (in place) on x laid out [tok][head][128]. Also folds in an output
// scale (1/sqrt(HD) for q). Precise: inv_freq in fp64, range reduction in
// fp64 so --use_fast_math cannot corrupt sin/cos of large angles.
// position_ids is int32 (JAX default x64-disabled demotes int64 -> int32).
// ---------------------------------------------------------------------------
__global__ void rope_kernel(float* __restrict__ x,
                            const int* __restrict__ pos_ids,
                            int nheads, int total, float outscale)
{
    int idx = blockIdx.x * blockDim.x + threadIdx.x;
    if (idx >= total) return;
    int j = idx & 63;                  // rotary pair index 0..63
    int t = idx >> 6;                  // tok*nheads + head
    int tok = t / nheads;

    int pos = pos_ids[tok];

    // inv_freq = 10000^(-j/64), computed in fp64 then rounded to fp32
    // (matches reference's fp32 inv_freq to ~1 ulp)
    float invf = (float)exp(-(double)j * (9.210340371976184 / 64.0));
    float angf = (float)pos * invf;    // fp32 angle, same rounding as reference
    // Precise range reduction in fp64, then fp32 sincos on small argument
    double r = remainder((double)angf, 6.283185307179586);
    float c, s;
    sincosf((float)r, &s, &c);

    float* base = x + (size_t)t * HD;
    float x1 = base[j];
    float x2 = base[j + 64];
    base[j]      = (x1 * c - x2 * s) * outscale;
    base[j + 64] = (x2 * c + x1 * s) * outscale;
}

// ---------------------------------------------------------------------------
// Flash attention (causal, GQA). One block = 64 queries for one (b, h).
// 128 threads: ty=tid>>3 (rows ty*4..+3), tx=tid&7.
//   S tile: 64x32 keys per iteration, micro 4x4 per thread.
//   O tile: 64x128, micro 4x16 per thread.
// q already scaled by 1/sqrt(HD).
// ---------------------------------------------------------------------------
__global__ void __launch_bounds__(128) flash_kernel(
    const float* __restrict__ Q, const float* __restrict__ K,
    const float* __restrict__ V, float* __restrict__ O)
{
    const int qt  = blockIdx.x;        // query tile (64 wide)
    const int h   = blockIdx.y;
    const int b   = blockIdx.z;
    const int hk  = h / (NH / NKV);
    const int tid = threadIdx.x;
    const int ty  = tid >> 3;          // 0..15
    const int tx  = tid & 7;           // 0..7
    const int q0  = qt * 64;

    __shared__ float sA[64 * 33];      // Q chunk [64][32] (pad 33) / P [64][32]
    __shared__ float sB[32 * 128];     // K chunk (transposed, stride 36) / V tile [32][128]

    float acc_o[4][16];
    float m_i[4], l_i[4];
#pragma unroll
    for (int i = 0; i < 4; i++) {
        m_i[i] = -1e30f; l_i[i] = 0.0f;
#pragma unroll
        for (int j = 0; j < 16; j++) acc_o[i][j] = 0.0f;
    }

    const float* qbase = Q + ((size_t)(b * SEQ + q0) * NH + h) * HD;
    const float* kbase = K + ((size_t)(b * SEQ) * NKV + hk) * HD;
    const float* vbase = V + ((size_t)(b * SEQ) * NKV + hk) * HD;
    const int qstride = NH * HD;       // 2048
    const int kstride = NKV * HD;      // 512

    const int nkt = 2 * qt + 2;        // 32-wide key tiles needed (causal)

    for (int kt = 0; kt < nkt; kt++) {
        const int k0 = kt * 32;

        float s_acc[4][4];
#pragma unroll
        for (int i = 0; i < 4; i++)
#pragma unroll
            for (int j = 0; j < 4; j++) s_acc[i][j] = 0.0f;

        // ---- S = Q K^T over 4 d-chunks of 32 ----
        for (int dc = 0; dc < 4; dc++) {
            // Q chunk 64x32 -> sA[m][d] (512 float4, 4 per thread)
#pragma unroll
            for (int i = 0; i < 4; i++) {
                int e  = i * 128 + tid;
                int m  = e >> 3;
                int c4 = (e & 7) * 4;
                float4 vq = *(const float4*)&qbase[(size_t)m * qstride + dc * 32 + c4];
                sA[m * 33 + c4 + 0] = vq.x;
                sA[m * 33 + c4 + 1] = vq.y;
                sA[m * 33 + c4 + 2] = vq.z;
                sA[m * 33 + c4 + 3] = vq.w;
            }
            // K chunk 32x32 -> transposed sB[d*36 + n] (256 float4, 2/thread)
#pragma unroll
            for (int i = 0; i < 2; i++) {
                int e  = i * 128 + tid;
                int n  = e >> 3;
                int c4 = (e & 7) * 4;
                float4 vk = *(const float4*)&kbase[(size_t)(k0 + n) * kstride + dc * 32 + c4];
                sB[(c4 + 0) * 36 + n] = vk.x;
                sB[(c4 + 1) * 36 + n] = vk.y;
                sB[(c4 + 2) * 36 + n] = vk.z;
                sB[(c4 + 3) * 36 + n] = vk.w;
            }
            __syncthreads();

#pragma unroll
            for (int kk = 0; kk < 32; kk++) {
                float a[4];
#pragma unroll
                for (int i = 0; i < 4; i++) a[i] = sA[(ty * 4 + i) * 33 + kk];
                float4 b4 = *(const float4*)&sB[kk * 36 + tx * 4];
                float bb[4] = {b4.x, b4.y, b4.z, b4.w};
#pragma unroll
                for (int i = 0; i < 4; i++)
#pragma unroll
                    for (int j = 0; j < 4; j++)
                        s_acc[i][j] += a[i] * bb[j];
            }
            __syncthreads();
        }

        // ---- causal mask (only diagonal tiles) ----
        if (k0 + 31 > q0) {
#pragma unroll
            for (int i = 0; i < 4; i++)
#pragma unroll
                for (int j = 0; j < 4; j++)
                    if (k0 + tx * 4 + j > q0 + ty * 4 + i)
                        s_acc[i][j] = -1e30f;
        }

        // ---- online softmax + write P into sA ----
#pragma unroll
        for (int i = 0; i < 4; i++) {
            float tm = fmaxf(fmaxf(s_acc[i][0], s_acc[i][1]),
                             fmaxf(s_acc[i][2], s_acc[i][3]));
            tm = fmaxf(tm, __shfl_xor_sync(0xffffffffu, tm, 1));
            tm = fmaxf(tm, __shfl_xor_sync(0xffffffffu, tm, 2));
            tm = fmaxf(tm, __shfl_xor_sync(0xffffffffu, tm, 4));
            float mn = fmaxf(m_i[i], tm);
            float sc = __expf(m_i[i] - mn);
            float rs = 0.0f;
#pragma unroll
            for (int j = 0; j < 4; j++) {
                float p = __expf(s_acc[i][j] - mn);
                s_acc[i][j] = p;
                rs += p;
            }
            rs += __shfl_xor_sync(0xffffffffu, rs, 1);
            rs += __shfl_xor_sync(0xffffffffu, rs, 2);
            rs += __shfl_xor_sync(0xffffffffu, rs, 4);
            l_i[i] = l_i[i] * sc + rs;
            m_i[i] = mn;
#pragma unroll
            for (int j = 0; j < 16; j++) acc_o[i][j] *= sc;
#pragma unroll
            for (int j = 0; j < 4; j++)
                sA[(ty * 4 + i) * 33 + tx * 4 + j] = s_acc[i][j];
        }

        // ---- load V tile 32x128 into sB ----
#pragma unroll
        for (int i = 0; i < 8; i++) {
            int e  = i * 128 + tid;          // float4 index, 1024 total
            int n  = e >> 5;
            int c4 = (e & 31) * 4;
            *(float4*)&sB[n * 128 + c4] =
                *(const float4*)&vbase[(size_t)(k0 + n) * kstride + c4];
        }
        __syncthreads();

        // ---- O += P @ V ----
#pragma unroll
        for (int n = 0; n < 32; n++) {
            float p[4];
#pragma unroll
            for (int i = 0; i < 4; i++) p[i] = sA[(ty * 4 + i) * 33 + n];
            float4 v0 = *(const float4*)&sB[n * 128 + tx * 16];
            float4 v1 = *(const float4*)&sB[n * 128 + tx * 16 + 4];
            float4 v2 = *(const float4*)&sB[n * 128 + tx * 16 + 8];
            float4 v3 = *(const float4*)&sB[n * 128 + tx * 16 + 12];
            float vv[16] = {v0.x, v0.y, v0.z, v0.w, v1.x, v1.y, v1.z, v1.w,
                            v2.x, v2.y, v2.z, v2.w, v3.x, v3.y, v3.z, v3.w};
#pragma unroll
            for (int i = 0; i < 4; i++)
#pragma unroll
                for (int j = 0; j < 16; j++)
                    acc_o[i][j] += p[i] * vv[j];
        }
        __syncthreads();   // before next iteration overwrites sA/sB
    }

    // ---- epilogue: O /= l, write out ----
    float* obase = O + ((size_t)(b * SEQ + q0) * NH + h) * HD;
#pragma unroll
    for (int i = 0; i < 4; i++) {
        float inv_l = 1.0f / l_i[i];
        size_t row = (size_t)(ty * 4 + i) * qstride + tx * 16;
#pragma unroll
        for (int j4 = 0; j4 < 4; j4++) {
            float4 o = {acc_o[i][j4 * 4 + 0] * inv_l,
                        acc_o[i][j4 * 4 + 1] * inv_l,
                        acc_o[i][j4 * 4 + 2] * inv_l,
                        acc_o[i][j4 * 4 + 3] * inv_l};
            *(float4*)&obase[row + j4 * 4] = o;
        }
    }
}

// ---------------------------------------------------------------------------
// Launch
// ---------------------------------------------------------------------------
extern "C" void kernel_launch(void* const* d_in, const int* in_sizes, int n_in,
                              void* d_out, int out_size)
{
    const float* hs  = (const float*)d_in[0];
    const int*   pos = (const int*)d_in[1];   // int32 (JAX x64-disabled)
    const float* Wq  = (const float*)d_in[2];
    const float* Wk  = (const float*)d_in[3];
    const float* Wv  = (const float*)d_in[4];
    const float* Wo  = (const float*)d_in[5];
    float*       out = (float*)d_out;

    float *q, *k, *v, *attn;
    cudaGetSymbolAddress((void**)&q,    g_q);
    cudaGetSymbolAddress((void**)&k,    g_k);
    cudaGetSymbolAddress((void**)&v,    g_v);
    cudaGetSymbolAddress((void**)&attn, g_attn);

    // QKV projections
    sgemm_kernel<<<dim3(2048 / 64, NTOK / 64), 128>>>(hs, Wq, q, NTOK, 2048, HSZ);
    sgemm_kernel<<<dim3(512  / 64, NTOK / 64), 128>>>(hs, Wk, k, NTOK, 512,  HSZ);
    sgemm_kernel<<<dim3(512  / 64, NTOK / 64), 128>>>(hs, Wv, v, NTOK, 512,  HSZ);

    // RoPE (q also gets the 1/sqrt(HD) attention scale folded in)
    {
        int total_q = NTOK * NH * 64;
        int total_k = NTOK * NKV * 64;
        rope_kernel<<<(total_q + 255) / 256, 256>>>(q, pos, NH, total_q,
                                                    0.08838834764831845f);
        rope_kernel<<<(total_k + 255) / 256, 256>>>(k, pos, NKV, total_k, 1.0f);
    }

    // Causal GQA attention
    flash_kernel<<<dim3(SEQ / 64, NH, BATCH), 128>>>(q, k, v, attn);

    // Output projection
    sgemm_kernel<<<dim3(2048 / 64, NTOK / 64), 128>>>(attn, Wo, out, NTOK, 2048, HSZ);
}

// round 5
// speedup vs baseline: 1.2998x; 1.2998x over previous
#include <cuda_runtime.h>
#include <math.h>

// Problem constants (fixed shapes)
#define HSZ   2048
#define NH    16
#define NKV   4
#define HD    128
#define BATCH 2
#define SEQ   2048
#define NTOK  (BATCH*SEQ)          // 4096

typedef unsigned int u32;

// Scratch (device globals; allocation is forbidden)
__device__ float g_q[(size_t)NTOK*NH*HD];     // 33.5 MB
__device__ float g_k[(size_t)NTOK*NKV*HD];    //  8.4 MB
__device__ float g_v[(size_t)NTOK*NKV*HD];    //  8.4 MB
__device__ float g_attn[(size_t)NTOK*NH*HD];  // 33.5 MB
// Pre-transposed + tf32-split weights: W^T stored [N][K], hi and lo parts.
#define WT_TOTAL 10485760
#define WT_OFF_Q 0
#define WT_OFF_K 4194304
#define WT_OFF_V 5242880
#define WT_OFF_O 6291456
__device__ float g_wt_hi[(size_t)WT_TOTAL];   // 41.9 MB
__device__ float g_wt_lo[(size_t)WT_TOTAL];   // 41.9 MB

// ---------------------------------------------------------------------------
// Helpers
// ---------------------------------------------------------------------------
__device__ __forceinline__ float tf32_rna(float x) {
    u32 u = __float_as_uint(x), r;
    asm("cvt.rna.tf32.f32 %0, %1;" : "=r"(r) : "r"(u));
    return __uint_as_float(r);
}

// D += A(16x8 tf32) * B(8x8 tf32), fp32 accum. row.col fragments.
__device__ __forceinline__ void mma_tf32(float* d, const u32* a, const u32* b) {
    asm volatile(
        "mma.sync.aligned.m16n8k8.row.col.f32.tf32.tf32.f32 "
        "{%0,%1,%2,%3}, {%4,%5,%6,%7}, {%8,%9}, {%0,%1,%2,%3};"
        : "+f"(d[0]), "+f"(d[1]), "+f"(d[2]), "+f"(d[3])
        : "r"(a[0]), "r"(a[1]), "r"(a[2]), "r"(a[3]), "r"(b[0]), "r"(b[1]));
}

// ---------------------------------------------------------------------------
// Weight transpose + tf32 hi/lo split: W[K][N] -> Th[N][K], Tl[N][K]
// block (32,8), grid (N/32, K/32)
// ---------------------------------------------------------------------------
__global__ void transpose_split_kernel(const float* __restrict__ W,
                                       float* __restrict__ Th,
                                       float* __restrict__ Tl,
                                       int K, int N)
{
    __shared__ float t[32][33];
    const int bx = blockIdx.x * 32;   // n
    const int by = blockIdx.y * 32;   // k
    const int tx = threadIdx.x, ty = threadIdx.y;
#pragma unroll
    for (int j = 0; j < 4; j++)
        t[ty + j * 8][tx] = W[(size_t)(by + ty + j * 8) * N + bx + tx];
    __syncthreads();
#pragma unroll
    for (int j = 0; j < 4; j++) {
        float v = t[tx][ty + j * 8];
        float h = tf32_rna(v);
        float l = tf32_rna(v - h);
        size_t o = (size_t)(bx + ty + j * 8) * K + by + tx;
        Th[o] = h;
        Tl[o] = l;
    }
}

// ---------------------------------------------------------------------------
// mma.sync tf32 GEMM (3xTF32): C[M,N] = A[M,2048] @ Bt[N,2048]^T
// A row-major fp32 (split hi/lo in regs on load), Bt pre-split hi/lo [N][K].
// CTA tile 128x128, BK=16, 256 threads (8 warps: 4 along M x 2 along N).
// Warp tile 32x64 -> 2 m-subtiles x 8 n-subtiles of m16n8k8.
// smem layouts [row][20] (K-minor, pad 20) -> conflict-free frag loads.
// ---------------------------------------------------------------------------
#define GK 2048

__global__ void __launch_bounds__(256, 2) gemm_mma_kernel(
    const float* __restrict__ A,
    const float* __restrict__ Bth,
    const float* __restrict__ Btl,
    float* __restrict__ C, int N)
{
    __shared__ float sAh[128][20], sAl[128][20];
    __shared__ float sBh[128][20], sBl[128][20];

    const int tid   = threadIdx.x;
    const int lane  = tid & 31;
    const int wid   = tid >> 5;
    const int wm    = wid >> 1;            // 0..3
    const int wn    = wid & 1;             // 0..1
    const int lane4 = lane >> 2;           // 0..7 (groupID)
    const int lanem = lane & 3;            // 0..3
    const int m0    = blockIdx.y * 128;
    const int n0    = blockIdx.x * 128;

    float acc[2][8][4];
#pragma unroll
    for (int mt = 0; mt < 2; mt++)
#pragma unroll
        for (int nt = 0; nt < 8; nt++)
#pragma unroll
            for (int r = 0; r < 4; r++) acc[mt][nt][r] = 0.0f;

    for (int k0 = 0; k0 < GK; k0 += 16) {
        // ---- load A tile 128x16 fp32, split hi/lo in regs, store smem ----
#pragma unroll
        for (int i = 0; i < 2; i++) {
            int e  = i * 256 + tid;        // float4 index (512 total)
            int m  = e >> 2;
            int kc = (e & 3) * 4;
            float4 v = *(const float4*)&A[(size_t)(m0 + m) * GK + k0 + kc];
            float4 h, l;
            h.x = tf32_rna(v.x); l.x = tf32_rna(v.x - h.x);
            h.y = tf32_rna(v.y); l.y = tf32_rna(v.y - h.y);
            h.z = tf32_rna(v.z); l.z = tf32_rna(v.z - h.z);
            h.w = tf32_rna(v.w); l.w = tf32_rna(v.w - h.w);
            *(float4*)&sAh[m][kc] = h;
            *(float4*)&sAl[m][kc] = l;
        }
        // ---- load B tiles 128x16 (pre-split) ----
#pragma unroll
        for (int i = 0; i < 2; i++) {
            int e  = i * 256 + tid;
            int n  = e >> 2;
            int kc = (e & 3) * 4;
            *(float4*)&sBh[n][kc] =
                *(const float4*)&Bth[(size_t)(n0 + n) * GK + k0 + kc];
            *(float4*)&sBl[n][kc] =
                *(const float4*)&Btl[(size_t)(n0 + n) * GK + k0 + kc];
        }
        __syncthreads();

        // ---- compute: two k8 steps ----
#pragma unroll
        for (int kh = 0; kh < 2; kh++) {
            const int kb = kh * 8;
            u32 ah[2][4], al[2][4];
#pragma unroll
            for (int mt = 0; mt < 2; mt++) {
                int r = wm * 32 + mt * 16 + lane4;
                ah[mt][0] = __float_as_uint(sAh[r    ][kb + lanem]);
                ah[mt][1] = __float_as_uint(sAh[r + 8][kb + lanem]);
                ah[mt][2] = __float_as_uint(sAh[r    ][kb + 4 + lanem]);
                ah[mt][3] = __float_as_uint(sAh[r + 8][kb + 4 + lanem]);
                al[mt][0] = __float_as_uint(sAl[r    ][kb + lanem]);
                al[mt][1] = __float_as_uint(sAl[r + 8][kb + lanem]);
                al[mt][2] = __float_as_uint(sAl[r    ][kb + 4 + lanem]);
                al[mt][3] = __float_as_uint(sAl[r + 8][kb + 4 + lanem]);
            }
#pragma unroll
            for (int nt = 0; nt < 8; nt++) {
                int cn = wn * 64 + nt * 8 + lane4;
                u32 bh[2], bl[2];
                bh[0] = __float_as_uint(sBh[cn][kb + lanem]);
                bh[1] = __float_as_uint(sBh[cn][kb + 4 + lanem]);
                bl[0] = __float_as_uint(sBl[cn][kb + lanem]);
                bl[1] = __float_as_uint(sBl[cn][kb + 4 + lanem]);
#pragma unroll
                for (int mt = 0; mt < 2; mt++) {
                    mma_tf32(acc[mt][nt], ah[mt], bh);   // hi*hi
                    mma_tf32(acc[mt][nt], ah[mt], bl);   // hi*lo
                    mma_tf32(acc[mt][nt], al[mt], bh);   // lo*hi
                }
            }
        }
        __syncthreads();
    }

    // ---- epilogue ----
#pragma unroll
    for (int mt = 0; mt < 2; mt++) {
#pragma unroll
        for (int nt = 0; nt < 8; nt++) {
            int r  = m0 + wm * 32 + mt * 16 + lane4;
            int cb = n0 + wn * 64 + nt * 8 + lanem * 2;
            float2 lo = {acc[mt][nt][0], acc[mt][nt][1]};
            float2 hi = {acc[mt][nt][2], acc[mt][nt][3]};
            *(float2*)&C[(size_t)r * N + cb]       = lo;
            *(float2*)&C[(size_t)(r + 8) * N + cb] = hi;
        }
    }
}

// ---------------------------------------------------------------------------
// RoPE (in place). position_ids is int32. Folds output scale into q.
// ---------------------------------------------------------------------------
__global__ void rope_kernel(float* __restrict__ x,
                            const int* __restrict__ pos_ids,
                            int nheads, int total, float outscale)
{
    int idx = blockIdx.x * blockDim.x + threadIdx.x;
    if (idx >= total) return;
    int j = idx & 63;
    int t = idx >> 6;
    int tok = t / nheads;

    int pos = pos_ids[tok];

    float invf = (float)exp(-(double)j * (9.210340371976184 / 64.0));
    float angf = (float)pos * invf;
    double r = remainder((double)angf, 6.283185307179586);
    float c, s;
    sincosf((float)r, &s, &c);

    float* base = x + (size_t)t * HD;
    float x1 = base[j];
    float x2 = base[j + 64];
    base[j]      = (x1 * c - x2 * s) * outscale;
    base[j + 64] = (x2 * c + x1 * s) * outscale;
}

// ---------------------------------------------------------------------------
// Flash attention (causal, GQA) — unchanged from passing R3 kernel.
// ---------------------------------------------------------------------------
__global__ void __launch_bounds__(128) flash_kernel(
    const float* __restrict__ Q, const float* __restrict__ K,
    const float* __restrict__ V, float* __restrict__ O)
{
    const int qt  = blockIdx.x;
    const int h   = blockIdx.y;
    const int b   = blockIdx.z;
    const int hk  = h / (NH / NKV);
    const int tid = threadIdx.x;
    const int ty  = tid >> 3;
    const int tx  = tid & 7;
    const int q0  = qt * 64;

    __shared__ float sA[64 * 33];
    __shared__ float sB[32 * 128];

    float acc_o[4][16];
    float m_i[4], l_i[4];
#pragma unroll
    for (int i = 0; i < 4; i++) {
        m_i[i] = -1e30f; l_i[i] = 0.0f;
#pragma unroll
        for (int j = 0; j < 16; j++) acc_o[i][j] = 0.0f;
    }

    const float* qbase = Q + ((size_t)(b * SEQ + q0) * NH + h) * HD;
    const float* kbase = K + ((size_t)(b * SEQ) * NKV + hk) * HD;
    const float* vbase = V + ((size_t)(b * SEQ) * NKV + hk) * HD;
    const int qstride = NH * HD;
    const int kstride = NKV * HD;

    const int nkt = 2 * qt + 2;

    for (int kt = 0; kt < nkt; kt++) {
        const int k0 = kt * 32;

        float s_acc[4][4];
#pragma unroll
        for (int i = 0; i < 4; i++)
#pragma unroll
            for (int j = 0; j < 4; j++) s_acc[i][j] = 0.0f;

        for (int dc = 0; dc < 4; dc++) {
#pragma unroll
            for (int i = 0; i < 4; i++) {
                int e  = i * 128 + tid;
                int m  = e >> 3;
                int c4 = (e & 7) * 4;
                float4 vq = *(const float4*)&qbase[(size_t)m * qstride + dc * 32 + c4];
                sA[m * 33 + c4 + 0] = vq.x;
                sA[m * 33 + c4 + 1] = vq.y;
                sA[m * 33 + c4 + 2] = vq.z;
                sA[m * 33 + c4 + 3] = vq.w;
            }
#pragma unroll
            for (int i = 0; i < 2; i++) {
                int e  = i * 128 + tid;
                int n  = e >> 3;
                int c4 = (e & 7) * 4;
                float4 vk = *(const float4*)&kbase[(size_t)(k0 + n) * kstride + dc * 32 + c4];
                sB[(c4 + 0) * 36 + n] = vk.x;
                sB[(c4 + 1) * 36 + n] = vk.y;
                sB[(c4 + 2) * 36 + n] = vk.z;
                sB[(c4 + 3) * 36 + n] = vk.w;
            }
            __syncthreads();

#pragma unroll
            for (int kk = 0; kk < 32; kk++) {
                float a[4];
#pragma unroll
                for (int i = 0; i < 4; i++) a[i] = sA[(ty * 4 + i) * 33 + kk];
                float4 b4 = *(const float4*)&sB[kk * 36 + tx * 4];
                float bb[4] = {b4.x, b4.y, b4.z, b4.w};
#pragma unroll
                for (int i = 0; i < 4; i++)
#pragma unroll
                    for (int j = 0; j < 4; j++)
                        s_acc[i][j] += a[i] * bb[j];
            }
            __syncthreads();
        }

        if (k0 + 31 > q0) {
#pragma unroll
            for (int i = 0; i < 4; i++)
#pragma unroll
                for (int j = 0; j < 4; j++)
                    if (k0 + tx * 4 + j > q0 + ty * 4 + i)
                        s_acc[i][j] = -1e30f;
        }

#pragma unroll
        for (int i = 0; i < 4; i++) {
            float tm = fmaxf(fmaxf(s_acc[i][0], s_acc[i][1]),
                             fmaxf(s_acc[i][2], s_acc[i][3]));
            tm = fmaxf(tm, __shfl_xor_sync(0xffffffffu, tm, 1));
            tm = fmaxf(tm, __shfl_xor_sync(0xffffffffu, tm, 2));
            tm = fmaxf(tm, __shfl_xor_sync(0xffffffffu, tm, 4));
            float mn = fmaxf(m_i[i], tm);
            float sc = __expf(m_i[i] - mn);
            float rs = 0.0f;
#pragma unroll
            for (int j = 0; j < 4; j++) {
                float p = __expf(s_acc[i][j] - mn);
                s_acc[i][j] = p;
                rs += p;
            }
            rs += __shfl_xor_sync(0xffffffffu, rs, 1);
            rs += __shfl_xor_sync(0xffffffffu, rs, 2);
            rs += __shfl_xor_sync(0xffffffffu, rs, 4);
            l_i[i] = l_i[i] * sc + rs;
            m_i[i] = mn;
#pragma unroll
            for (int j = 0; j < 16; j++) acc_o[i][j] *= sc;
#pragma unroll
            for (int j = 0; j < 4; j++)
                sA[(ty * 4 + i) * 33 + tx * 4 + j] = s_acc[i][j];
        }

#pragma unroll
        for (int i = 0; i < 8; i++) {
            int e  = i * 128 + tid;
            int n  = e >> 5;
            int c4 = (e & 31) * 4;
            *(float4*)&sB[n * 128 + c4] =
                *(const float4*)&vbase[(size_t)(k0 + n) * kstride + c4];
        }
        __syncthreads();

#pragma unroll
        for (int n = 0; n < 32; n++) {
            float p[4];
#pragma unroll
            for (int i = 0; i < 4; i++) p[i] = sA[(ty * 4 + i) * 33 + n];
            float4 v0 = *(const float4*)&sB[n * 128 + tx * 16];
            float4 v1 = *(const float4*)&sB[n * 128 + tx * 16 + 4];
            float4 v2 = *(const float4*)&sB[n * 128 + tx * 16 + 8];
            float4 v3 = *(const float4*)&sB[n * 128 + tx * 16 + 12];
            float vv[16] = {v0.x, v0.y, v0.z, v0.w, v1.x, v1.y, v1.z, v1.w,
                            v2.x, v2.y, v2.z, v2.w, v3.x, v3.y, v3.z, v3.w};
#pragma unroll
            for (int i = 0; i < 4; i++)
#pragma unroll
                for (int j = 0; j < 16; j++)
                    acc_o[i][j] += p[i] * vv[j];
        }
        __syncthreads();
    }

    float* obase = O + ((size_t)(b * SEQ + q0) * NH + h) * HD;
#pragma unroll
    for (int i = 0; i < 4; i++) {
        float inv_l = 1.0f / l_i[i];
        size_t row = (size_t)(ty * 4 + i) * qstride + tx * 16;
#pragma unroll
        for (int j4 = 0; j4 < 4; j4++) {
            float4 o = {acc_o[i][j4 * 4 + 0] * inv_l,
                        acc_o[i][j4 * 4 + 1] * inv_l,
                        acc_o[i][j4 * 4 + 2] * inv_l,
                        acc_o[i][j4 * 4 + 3] * inv_l};
            *(float4*)&obase[row + j4 * 4] = o;
        }
    }
}

// ---------------------------------------------------------------------------
// Launch
// ---------------------------------------------------------------------------
extern "C" void kernel_launch(void* const* d_in, const int* in_sizes, int n_in,
                              void* d_out, int out_size)
{
    const float* hs  = (const float*)d_in[0];
    const int*   pos = (const int*)d_in[1];   // int32 (JAX x64-disabled)
    const float* Wq  = (const float*)d_in[2];
    const float* Wk  = (const float*)d_in[3];
    const float* Wv  = (const float*)d_in[4];
    const float* Wo  = (const float*)d_in[5];
    float*       out = (float*)d_out;

    float *q, *k, *v, *attn, *wth, *wtl;
    cudaGetSymbolAddress((void**)&q,    g_q);
    cudaGetSymbolAddress((void**)&k,    g_k);
    cudaGetSymbolAddress((void**)&v,    g_v);
    cudaGetSymbolAddress((void**)&attn, g_attn);
    cudaGetSymbolAddress((void**)&wth,  g_wt_hi);
    cudaGetSymbolAddress((void**)&wtl,  g_wt_lo);

    // Weight transpose + tf32 split
    transpose_split_kernel<<<dim3(2048/32, 2048/32), dim3(32, 8)>>>(
        Wq, wth + WT_OFF_Q, wtl + WT_OFF_Q, HSZ, 2048);
    transpose_split_kernel<<<dim3(512/32, 2048/32), dim3(32, 8)>>>(
        Wk, wth + WT_OFF_K, wtl + WT_OFF_K, HSZ, 512);
    transpose_split_kernel<<<dim3(512/32, 2048/32), dim3(32, 8)>>>(
        Wv, wth + WT_OFF_V, wtl + WT_OFF_V, HSZ, 512);
    transpose_split_kernel<<<dim3(2048/32, 2048/32), dim3(32, 8)>>>(
        Wo, wth + WT_OFF_O, wtl + WT_OFF_O, HSZ, 2048);

    // QKV projections (mma.sync tf32, 3xTF32)
    gemm_mma_kernel<<<dim3(2048/128, NTOK/128), 256>>>(
        hs, wth + WT_OFF_Q, wtl + WT_OFF_Q, q, 2048);
    gemm_mma_kernel<<<dim3(512/128, NTOK/128), 256>>>(
        hs, wth + WT_OFF_K, wtl + WT_OFF_K, k, 512);
    gemm_mma_kernel<<<dim3(512/128, NTOK/128), 256>>>(
        hs, wth + WT_OFF_V, wtl + WT_OFF_V, v, 512);

    // RoPE (q also gets the 1/sqrt(HD) attention scale folded in)
    {
        int total_q = NTOK * NH * 64;
        int total_k = NTOK * NKV * 64;
        rope_kernel<<<(total_q + 255) / 256, 256>>>(q, pos, NH, total_q,
                                                    0.08838834764831845f);
        rope_kernel<<<(total_k + 255) / 256, 256>>>(k, pos, NKV, total_k, 1.0f);
    }

    // Causal GQA attention
    flash_kernel<<<dim3(SEQ / 64, NH, BATCH), 128>>>(q, k, v, attn);

    // Output projection (mma.sync tf32, 3xTF32)
    gemm_mma_kernel<<<dim3(2048/128, NTOK/128), 256>>>(
        attn, wth + WT_OFF_O, wtl + WT_OFF_O, out, 2048);
}

// round 6
// speedup vs baseline: 2.1937x; 1.6878x over previous
#include <cuda_runtime.h>
#include <cuda_bf16.h>
#include <math.h>

// Problem constants (fixed shapes)
#define HSZ   2048
#define NH    16
#define NKV   4
#define HD    128
#define BATCH 2
#define SEQ   2048
#define NTOK  (BATCH*SEQ)          // 4096

typedef unsigned int u32;
typedef __nv_bfloat16 bf16;

// Scratch (device globals; allocation is forbidden)
__device__ float g_q[(size_t)NTOK*NH*HD];
__device__ float g_k[(size_t)NTOK*NKV*HD];
__device__ float g_v[(size_t)NTOK*NKV*HD];
__device__ float g_attn[(size_t)NTOK*NH*HD];
// Pre-transposed + tf32-split weights
#define WT_TOTAL 10485760
#define WT_OFF_Q 0
#define WT_OFF_K 4194304
#define WT_OFF_V 5242880
#define WT_OFF_O 6291456
__device__ float g_wt_hi[(size_t)WT_TOTAL];
__device__ float g_wt_lo[(size_t)WT_TOTAL];
// bf16 hi/lo attention operands
__device__ bf16 g_qh[(size_t)NTOK*NH*HD],  g_ql[(size_t)NTOK*NH*HD];
__device__ bf16 g_kh[(size_t)NTOK*NKV*HD], g_kl[(size_t)NTOK*NKV*HD];
__device__ bf16 g_vth[(size_t)BATCH*NKV*HD*SEQ], g_vtl[(size_t)BATCH*NKV*HD*SEQ];

// ---------------------------------------------------------------------------
// Helpers
// ---------------------------------------------------------------------------
__device__ __forceinline__ float tf32_rna(float x) {
    u32 u = __float_as_uint(x), r;
    asm("cvt.rna.tf32.f32 %0, %1;" : "=r"(r) : "r"(u));
    return __uint_as_float(r);
}

__device__ __forceinline__ void mma_tf32(float* d, const u32* a, const u32* b) {
    asm volatile(
        "mma.sync.aligned.m16n8k8.row.col.f32.tf32.tf32.f32 "
        "{%0,%1,%2,%3}, {%4,%5,%6,%7}, {%8,%9}, {%0,%1,%2,%3};"
        : "+f"(d[0]), "+f"(d[1]), "+f"(d[2]), "+f"(d[3])
        : "r"(a[0]), "r"(a[1]), "r"(a[2]), "r"(a[3]), "r"(b[0]), "r"(b[1]));
}

__device__ __forceinline__ void mma_bf16(float* d, const u32* a, u32 b0, u32 b1) {
    asm volatile(
        "mma.sync.aligned.m16n8k16.row.col.f32.bf16.bf16.f32 "
        "{%0,%1,%2,%3}, {%4,%5,%6,%7}, {%8,%9}, {%0,%1,%2,%3};"
        : "+f"(d[0]), "+f"(d[1]), "+f"(d[2]), "+f"(d[3])
        : "r"(a[0]), "r"(a[1]), "r"(a[2]), "r"(a[3]), "r"(b0), "r"(b1));
}

__device__ __forceinline__ u32 pack_bf16(float a, float b) {
    u32 lo = (u32)__bfloat16_as_ushort(__float2bfloat16_rn(a));
    u32 hi = (u32)__bfloat16_as_ushort(__float2bfloat16_rn(b));
    return lo | (hi << 16);
}

// ---------------------------------------------------------------------------
// Weight transpose + tf32 hi/lo split: W[K][N] -> Th[N][K], Tl[N][K]
// ---------------------------------------------------------------------------
__global__ void transpose_split_kernel(const float* __restrict__ W,
                                       float* __restrict__ Th,
                                       float* __restrict__ Tl,
                                       int K, int N)
{
    __shared__ float t[32][33];
    const int bx = blockIdx.x * 32;
    const int by = blockIdx.y * 32;
    const int tx = threadIdx.x, ty = threadIdx.y;
#pragma unroll
    for (int j = 0; j < 4; j++)
        t[ty + j * 8][tx] = W[(size_t)(by + ty + j * 8) * N + bx + tx];
    __syncthreads();
#pragma unroll
    for (int j = 0; j < 4; j++) {
        float v = t[tx][ty + j * 8];
        float h = tf32_rna(v);
        float l = tf32_rna(v - h);
        size_t o = (size_t)(bx + ty + j * 8) * K + by + tx;
        Th[o] = h;
        Tl[o] = l;
    }
}

// ---------------------------------------------------------------------------
// mma.sync tf32 GEMM (3xTF32) — unchanged from passing R5 kernel.
// ---------------------------------------------------------------------------
#define GK 2048

__global__ void __launch_bounds__(256, 2) gemm_mma_kernel(
    const float* __restrict__ A,
    const float* __restrict__ Bth,
    const float* __restrict__ Btl,
    float* __restrict__ C, int N)
{
    __shared__ float sAh[128][20], sAl[128][20];
    __shared__ float sBh[128][20], sBl[128][20];

    const int tid   = threadIdx.x;
    const int lane  = tid & 31;
    const int wid   = tid >> 5;
    const int wm    = wid >> 1;
    const int wn    = wid & 1;
    const int lane4 = lane >> 2;
    const int lanem = lane & 3;
    const int m0    = blockIdx.y * 128;
    const int n0    = blockIdx.x * 128;

    float acc[2][8][4];
#pragma unroll
    for (int mt = 0; mt < 2; mt++)
#pragma unroll
        for (int nt = 0; nt < 8; nt++)
#pragma unroll
            for (int r = 0; r < 4; r++) acc[mt][nt][r] = 0.0f;

    for (int k0 = 0; k0 < GK; k0 += 16) {
#pragma unroll
        for (int i = 0; i < 2; i++) {
            int e  = i * 256 + tid;
            int m  = e >> 2;
            int kc = (e & 3) * 4;
            float4 v = *(const float4*)&A[(size_t)(m0 + m) * GK + k0 + kc];
            float4 h, l;
            h.x = tf32_rna(v.x); l.x = tf32_rna(v.x - h.x);
            h.y = tf32_rna(v.y); l.y = tf32_rna(v.y - h.y);
            h.z = tf32_rna(v.z); l.z = tf32_rna(v.z - h.z);
            h.w = tf32_rna(v.w); l.w = tf32_rna(v.w - h.w);
            *(float4*)&sAh[m][kc] = h;
            *(float4*)&sAl[m][kc] = l;
        }
#pragma unroll
        for (int i = 0; i < 2; i++) {
            int e  = i * 256 + tid;
            int n  = e >> 2;
            int kc = (e & 3) * 4;
            *(float4*)&sBh[n][kc] =
                *(const float4*)&Bth[(size_t)(n0 + n) * GK + k0 + kc];
            *(float4*)&sBl[n][kc] =
                *(const float4*)&Btl[(size_t)(n0 + n) * GK + k0 + kc];
        }
        __syncthreads();

#pragma unroll
        for (int kh = 0; kh < 2; kh++) {
            const int kb = kh * 8;
            u32 ah[2][4], al[2][4];
#pragma unroll
            for (int mt = 0; mt < 2; mt++) {
                int r = wm * 32 + mt * 16 + lane4;
                ah[mt][0] = __float_as_uint(sAh[r    ][kb + lanem]);
                ah[mt][1] = __float_as_uint(sAh[r + 8][kb + lanem]);
                ah[mt][2] = __float_as_uint(sAh[r    ][kb + 4 + lanem]);
                ah[mt][3] = __float_as_uint(sAh[r + 8][kb + 4 + lanem]);
                al[mt][0] = __float_as_uint(sAl[r    ][kb + lanem]);
                al[mt][1] = __float_as_uint(sAl[r + 8][kb + lanem]);
                al[mt][2] = __float_as_uint(sAl[r    ][kb + 4 + lanem]);
                al[mt][3] = __float_as_uint(sAl[r + 8][kb + 4 + lanem]);
            }
#pragma unroll
            for (int nt = 0; nt < 8; nt++) {
                int cn = wn * 64 + nt * 8 + lane4;
                u32 bh[2], bl[2];
                bh[0] = __float_as_uint(sBh[cn][kb + lanem]);
                bh[1] = __float_as_uint(sBh[cn][kb + 4 + lanem]);
                bl[0] = __float_as_uint(sBl[cn][kb + lanem]);
                bl[1] = __float_as_uint(sBl[cn][kb + 4 + lanem]);
#pragma unroll
                for (int mt = 0; mt < 2; mt++) {
                    mma_tf32(acc[mt][nt], ah[mt], bh);
                    mma_tf32(acc[mt][nt], ah[mt], bl);
                    mma_tf32(acc[mt][nt], al[mt], bh);
                }
            }
        }
        __syncthreads();
    }

#pragma unroll
    for (int mt = 0; mt < 2; mt++) {
#pragma unroll
        for (int nt = 0; nt < 8; nt++) {
            int r  = m0 + wm * 32 + mt * 16 + lane4;
            int cb = n0 + wn * 64 + nt * 8 + lanem * 2;
            float2 lo = {acc[mt][nt][0], acc[mt][nt][1]};
            float2 hi = {acc[mt][nt][2], acc[mt][nt][3]};
            *(float2*)&C[(size_t)r * N + cb]       = lo;
            *(float2*)&C[(size_t)(r + 8) * N + cb] = hi;
        }
    }
}

// ---------------------------------------------------------------------------
// RoPE + bf16 hi/lo split. Reads fp32 x [tok][head][HD], writes xh/xl bf16.
// outscale folds 1/sqrt(HD) into q.
// ---------------------------------------------------------------------------
__global__ void rope_split_kernel(const float* __restrict__ x,
                                  bf16* __restrict__ xh, bf16* __restrict__ xl,
                                  const int* __restrict__ pos_ids,
                                  int nheads, int total, float outscale)
{
    int idx = blockIdx.x * blockDim.x + threadIdx.x;
    if (idx >= total) return;
    int j = idx & 63;
    int t = idx >> 6;
    int tok = t / nheads;

    int pos = pos_ids[tok];

    float invf = (float)exp(-(double)j * (9.210340371976184 / 64.0));
    float angf = (float)pos * invf;
    double r = remainder((double)angf, 6.283185307179586);
    float c, s;
    sincosf((float)r, &s, &c);

    const float* base = x + (size_t)t * HD;
    float x1 = base[j];
    float x2 = base[j + 64];
    float o1 = (x1 * c - x2 * s) * outscale;
    float o2 = (x2 * c + x1 * s) * outscale;

    size_t o = (size_t)t * HD;
    bf16 h1 = __float2bfloat16_rn(o1);
    bf16 h2 = __float2bfloat16_rn(o2);
    xh[o + j]      = h1;
    xh[o + j + 64] = h2;
    xl[o + j]      = __float2bfloat16_rn(o1 - __bfloat162float(h1));
    xl[o + j + 64] = __float2bfloat16_rn(o2 - __bfloat162float(h2));
}

// ---------------------------------------------------------------------------
// V transpose + bf16 split: V[(b,s),hk,d] -> Vt[(b,hk),d,s] hi/lo bf16
// block (32,8), grid (SEQ/32, HD/32, BATCH*NKV)
// ---------------------------------------------------------------------------
__global__ void vt_split_kernel(const float* __restrict__ V,
                                bf16* __restrict__ Vth, bf16* __restrict__ Vtl)
{
    __shared__ float t[32][33];
    const int b  = blockIdx.z >> 2;
    const int hk = blockIdx.z & 3;
    const int s0 = blockIdx.x * 32;
    const int d0 = blockIdx.y * 32;
    const int tx = threadIdx.x, ty = threadIdx.y;
#pragma unroll
    for (int j = 0; j < 4; j++)
        t[ty + j * 8][tx] =
            V[((size_t)(b * SEQ + s0 + ty + j * 8) * NKV + hk) * HD + d0 + tx];
    __syncthreads();
#pragma unroll
    for (int j = 0; j < 4; j++) {
        float v = t[tx][ty + j * 8];
        bf16 h = __float2bfloat16_rn(v);
        size_t o = ((size_t)(b * NKV + hk) * HD + d0 + ty + j * 8) * SEQ + s0 + tx;
        Vth[o] = h;
        Vtl[o] = __float2bfloat16_rn(v - __bfloat162float(h));
    }
}

// ---------------------------------------------------------------------------
// Flash attention with mma.sync bf16 (3xBF16). Causal, GQA.
// CTA: 128 queries x one (b,h). 256 threads, 8 warps, warp tile 16 rows.
// K tiles of 64 keys. Q fragments in registers; K/Vt in padded smem.
// ---------------------------------------------------------------------------
#define KSTR 136     // smem K row stride (bf16)
#define VSTR 72      // smem Vt row stride (bf16)
#define SK_H 0
#define SK_L (64*KSTR)
#define SV_H (2*64*KSTR)
#define SV_L (2*64*KSTR + 128*VSTR)
#define FLASH_SMEM ((2*64*KSTR + 2*128*VSTR) * 2)   // 71680 bytes

__global__ void __launch_bounds__(256, 1) flash_mma_kernel(
    const bf16* __restrict__ Qh, const bf16* __restrict__ Ql,
    const bf16* __restrict__ Kh, const bf16* __restrict__ Kl,
    const bf16* __restrict__ Vth, const bf16* __restrict__ Vtl,
    float* __restrict__ O)
{
    extern __shared__ bf16 sm[];
    const int qt  = blockIdx.x;
    const int h   = blockIdx.y;
    const int b   = blockIdx.z;
    const int hk  = h >> 2;            // NH/NKV = 4
    const int tid = threadIdx.x;
    const int wid = tid >> 5;
    const int lane = tid & 31;
    const int g   = lane >> 2;         // groupID 0..7
    const int t4  = lane & 3;          // 0..3
    const int q0  = qt * 128;

    const int r0 = q0 + wid * 16 + g;  // this thread's rows
    const int r1 = r0 + 8;

    // ---- load Q fragments into registers (once) ----
    u32 qfh[8][4], qfl[8][4];
    {
        const size_t b0 = ((size_t)(b * SEQ + r0) * NH + h) * HD;
        const size_t b1 = ((size_t)(b * SEQ + r1) * NH + h) * HD;
#pragma unroll
        for (int s = 0; s < 8; s++) {
            int d0 = s * 16 + t4 * 2, d1 = d0 + 8;
            qfh[s][0] = *(const u32*)&Qh[b0 + d0];
            qfh[s][1] = *(const u32*)&Qh[b1 + d0];
            qfh[s][2] = *(const u32*)&Qh[b0 + d1];
            qfh[s][3] = *(const u32*)&Qh[b1 + d1];
            qfl[s][0] = *(const u32*)&Ql[b0 + d0];
            qfl[s][1] = *(const u32*)&Ql[b1 + d0];
            qfl[s][2] = *(const u32*)&Ql[b0 + d1];
            qfl[s][3] = *(const u32*)&Ql[b1 + d1];
        }
    }

    float oacc[16][4];
#pragma unroll
    for (int nt = 0; nt < 16; nt++)
#pragma unroll
        for (int r = 0; r < 4; r++) oacc[nt][r] = 0.0f;
    float m0 = -1e30f, m1 = -1e30f, l0 = 0.0f, l1 = 0.0f;

    const int nkt = 2 * qt + 2;

    for (int kt = 0; kt < nkt; kt++) {
        const int k0 = kt * 64;

        // ---- load K tile (64x128 bf16 hi+lo) ----
        {
            const size_t kb = ((size_t)(b * SEQ + k0) * NKV + hk) * HD;
#pragma unroll
            for (int i = 0; i < 8; i++) {
                int e  = i * 256 + tid;          // 0..2047 float4s
                int hl = e >> 10;
                int r  = (e >> 4) & 63;
                int c4 = e & 15;
                const bf16* src = hl ? Kl : Kh;
                bf16* dst = sm + (hl ? SK_L : SK_H);
                *(float4*)&dst[r * KSTR + c4 * 8] =
                    *(const float4*)&src[kb + (size_t)r * (NKV * HD) + c4 * 8];
            }
        }
        // ---- load Vt tile (128 d x 64 keys bf16 hi+lo) ----
        {
            const size_t vb = ((size_t)(b * NKV + hk) * HD) * SEQ + k0;
#pragma unroll
            for (int i = 0; i < 8; i++) {
                int e  = i * 256 + tid;
                int hl = e >> 10;
                int d  = (e >> 3) & 127;
                int c4 = e & 7;
                const bf16* src = hl ? Vtl : Vth;
                bf16* dst = sm + (hl ? SV_L : SV_H);
                *(float4*)&dst[d * VSTR + c4 * 8] =
                    *(const float4*)&src[vb + (size_t)d * SEQ + c4 * 8];
            }
        }
        __syncthreads();

        // Fully-masked warp? (all its rows < k0)
        const bool active = (k0 <= q0 + wid * 16 + 15);
        if (active) {
            // ---- S = Q K^T (3xBF16) ----
            float sacc[8][4];
#pragma unroll
            for (int j = 0; j < 8; j++)
#pragma unroll
                for (int r = 0; r < 4; r++) sacc[j][r] = 0.0f;

#pragma unroll
            for (int s = 0; s < 8; s++) {
#pragma unroll
                for (int j = 0; j < 8; j++) {
                    int key = j * 8 + g;
                    u32 bh0 = *(const u32*)&sm[SK_H + key * KSTR + s * 16 + t4 * 2];
                    u32 bh1 = *(const u32*)&sm[SK_H + key * KSTR + s * 16 + 8 + t4 * 2];
                    u32 bl0 = *(const u32*)&sm[SK_L + key * KSTR + s * 16 + t4 * 2];
                    u32 bl1 = *(const u32*)&sm[SK_L + key * KSTR + s * 16 + 8 + t4 * 2];
                    mma_bf16(sacc[j], qfh[s], bh0, bh1);
                    mma_bf16(sacc[j], qfh[s], bl0, bl1);
                    mma_bf16(sacc[j], qfl[s], bh0, bh1);
                }
            }

            // ---- causal mask (diagonal tiles only) ----
            if (k0 + 63 > q0) {
#pragma unroll
                for (int j = 0; j < 8; j++) {
                    int c0 = k0 + j * 8 + t4 * 2;
                    if (c0     > r0) sacc[j][0] = -1e30f;
                    if (c0 + 1 > r0) sacc[j][1] = -1e30f;
                    if (c0     > r1) sacc[j][2] = -1e30f;
                    if (c0 + 1 > r1) sacc[j][3] = -1e30f;
                }
            }

            // ---- online softmax (row stats within quad) ----
            float rm0 = -1e30f, rm1 = -1e30f;
#pragma unroll
            for (int j = 0; j < 8; j++) {
                rm0 = fmaxf(rm0, fmaxf(sacc[j][0], sacc[j][1]));
                rm1 = fmaxf(rm1, fmaxf(sacc[j][2], sacc[j][3]));
            }
            rm0 = fmaxf(rm0, __shfl_xor_sync(0xffffffffu, rm0, 1));
            rm0 = fmaxf(rm0, __shfl_xor_sync(0xffffffffu, rm0, 2));
            rm1 = fmaxf(rm1, __shfl_xor_sync(0xffffffffu, rm1, 1));
            rm1 = fmaxf(rm1, __shfl_xor_sync(0xffffffffu, rm1, 2));
            float mn0 = fmaxf(m0, rm0), mn1 = fmaxf(m1, rm1);
            float a0 = __expf(m0 - mn0), a1 = __expf(m1 - mn1);
            m0 = mn0; m1 = mn1;
            float rs0 = 0.0f, rs1 = 0.0f;
#pragma unroll
            for (int j = 0; j < 8; j++) {
                sacc[j][0] = __expf(sacc[j][0] - m0);
                sacc[j][1] = __expf(sacc[j][1] - m0);
                sacc[j][2] = __expf(sacc[j][2] - m1);
                sacc[j][3] = __expf(sacc[j][3] - m1);
                rs0 += sacc[j][0] + sacc[j][1];
                rs1 += sacc[j][2] + sacc[j][3];
            }
            rs0 += __shfl_xor_sync(0xffffffffu, rs0, 1);
            rs0 += __shfl_xor_sync(0xffffffffu, rs0, 2);
            rs1 += __shfl_xor_sync(0xffffffffu, rs1, 1);
            rs1 += __shfl_xor_sync(0xffffffffu, rs1, 2);
            l0 = l0 * a0 + rs0;
            l1 = l1 * a1 + rs1;
#pragma unroll
            for (int nt = 0; nt < 16; nt++) {
                oacc[nt][0] *= a0; oacc[nt][1] *= a0;
                oacc[nt][2] *= a1; oacc[nt][3] *= a1;
            }

            // ---- P fragments (C-layout -> A-layout, in registers) ----
            u32 pfh[4][4], pfl[4][4];
#pragma unroll
            for (int s = 0; s < 4; s++) {
                int j0 = 2 * s, j1 = 2 * s + 1;
                float h00, h01, h10, h11, h20, h21, h30, h31;
                h00 = __bfloat162float(__float2bfloat16_rn(sacc[j0][0]));
                h01 = __bfloat162float(__float2bfloat16_rn(sacc[j0][1]));
                h10 = __bfloat162float(__float2bfloat16_rn(sacc[j0][2]));
                h11 = __bfloat162float(__float2bfloat16_rn(sacc[j0][3]));
                h20 = __bfloat162float(__float2bfloat16_rn(sacc[j1][0]));
                h21 = __bfloat162float(__float2bfloat16_rn(sacc[j1][1]));
                h30 = __bfloat162float(__float2bfloat16_rn(sacc[j1][2]));
                h31 = __bfloat162float(__float2bfloat16_rn(sacc[j1][3]));
                pfh[s][0] = pack_bf16(h00, h01);
                pfh[s][1] = pack_bf16(h10, h11);
                pfh[s][2] = pack_bf16(h20, h21);
                pfh[s][3] = pack_bf16(h30, h31);
                pfl[s][0] = pack_bf16(sacc[j0][0] - h00, sacc[j0][1] - h01);
                pfl[s][1] = pack_bf16(sacc[j0][2] - h10, sacc[j0][3] - h11);
                pfl[s][2] = pack_bf16(sacc[j1][0] - h20, sacc[j1][1] - h21);
                pfl[s][3] = pack_bf16(sacc[j1][2] - h30, sacc[j1][3] - h31);
            }

            // ---- O += P V (3xBF16) ----
#pragma unroll
            for (int s = 0; s < 4; s++) {
#pragma unroll
                for (int nt = 0; nt < 16; nt++) {
                    int d = nt * 8 + g;
                    u32 vh0 = *(const u32*)&sm[SV_H + d * VSTR + s * 16 + t4 * 2];
                    u32 vh1 = *(const u32*)&sm[SV_H + d * VSTR + s * 16 + 8 + t4 * 2];
                    u32 vl0 = *(const u32*)&sm[SV_L + d * VSTR + s * 16 + t4 * 2];
                    u32 vl1 = *(const u32*)&sm[SV_L + d * VSTR + s * 16 + 8 + t4 * 2];
                    mma_bf16(oacc[nt], pfh[s], vh0, vh1);
                    mma_bf16(oacc[nt], pfh[s], vl0, vl1);
                    mma_bf16(oacc[nt], pfl[s], vh0, vh1);
                }
            }
        }
        __syncthreads();
    }

    // ---- epilogue ----
    float il0 = 1.0f / l0, il1 = 1.0f / l1;
    const size_t ob0 = ((size_t)(b * SEQ + r0) * NH + h) * HD;
    const size_t ob1 = ((size_t)(b * SEQ + r1) * NH + h) * HD;
#pragma unroll
    for (int nt = 0; nt < 16; nt++) {
        int cb = nt * 8 + t4 * 2;
        float2 lo = {oacc[nt][0] * il0, oacc[nt][1] * il0};
        float2 hi = {oacc[nt][2] * il1, oacc[nt][3] * il1};
        *(float2*)&O[ob0 + cb] = lo;
        *(float2*)&O[ob1 + cb] = hi;
    }
}

// ---------------------------------------------------------------------------
// Launch
// ---------------------------------------------------------------------------
extern "C" void kernel_launch(void* const* d_in, const int* in_sizes, int n_in,
                              void* d_out, int out_size)
{
    const float* hs  = (const float*)d_in[0];
    const int*   pos = (const int*)d_in[1];
    const float* Wq  = (const float*)d_in[2];
    const float* Wk  = (const float*)d_in[3];
    const float* Wv  = (const float*)d_in[4];
    const float* Wo  = (const float*)d_in[5];
    float*       out = (float*)d_out;

    float *q, *k, *v, *attn, *wth, *wtl;
    bf16 *qh, *ql, *kh, *kl, *vth, *vtl;
    cudaGetSymbolAddress((void**)&q,    g_q);
    cudaGetSymbolAddress((void**)&k,    g_k);
    cudaGetSymbolAddress((void**)&v,    g_v);
    cudaGetSymbolAddress((void**)&attn, g_attn);
    cudaGetSymbolAddress((void**)&wth,  g_wt_hi);
    cudaGetSymbolAddress((void**)&wtl,  g_wt_lo);
    cudaGetSymbolAddress((void**)&qh,   g_qh);
    cudaGetSymbolAddress((void**)&ql,   g_ql);
    cudaGetSymbolAddress((void**)&kh,   g_kh);
    cudaGetSymbolAddress((void**)&kl,   g_kl);
    cudaGetSymbolAddress((void**)&vth,  g_vth);
    cudaGetSymbolAddress((void**)&vtl,  g_vtl);

    cudaFuncSetAttribute(flash_mma_kernel,
                         cudaFuncAttributeMaxDynamicSharedMemorySize, FLASH_SMEM);

    // Weight transpose + tf32 split
    transpose_split_kernel<<<dim3(2048/32, 2048/32), dim3(32, 8)>>>(
        Wq, wth + WT_OFF_Q, wtl + WT_OFF_Q, HSZ, 2048);
    transpose_split_kernel<<<dim3(512/32, 2048/32), dim3(32, 8)>>>(
        Wk, wth + WT_OFF_K, wtl + WT_OFF_K, HSZ, 512);
    transpose_split_kernel<<<dim3(512/32, 2048/32), dim3(32, 8)>>>(
        Wv, wth + WT_OFF_V, wtl + WT_OFF_V, HSZ, 512);
    transpose_split_kernel<<<dim3(2048/32, 2048/32), dim3(32, 8)>>>(
        Wo, wth + WT_OFF_O, wtl + WT_OFF_O, HSZ, 2048);

    // QKV projections (mma.sync tf32, 3xTF32)
    gemm_mma_kernel<<<dim3(2048/128, NTOK/128), 256>>>(
        hs, wth + WT_OFF_Q, wtl + WT_OFF_Q, q, 2048);
    gemm_mma_kernel<<<dim3(512/128, NTOK/128), 256>>>(
        hs, wth + WT_OFF_K, wtl + WT_OFF_K, k, 512);
    gemm_mma_kernel<<<dim3(512/128, NTOK/128), 256>>>(
        hs, wth + WT_OFF_V, wtl + WT_OFF_V, v, 512);

    // RoPE + bf16 split (q gets 1/sqrt(HD) folded in); V transpose+split
    {
        int total_q = NTOK * NH * 64;
        int total_k = NTOK * NKV * 64;
        rope_split_kernel<<<(total_q + 255) / 256, 256>>>(
            q, qh, ql, pos, NH, total_q, 0.08838834764831845f);
        rope_split_kernel<<<(total_k + 255) / 256, 256>>>(
            k, kh, kl, pos, NKV, total_k, 1.0f);
        vt_split_kernel<<<dim3(SEQ/32, HD/32, BATCH*NKV), dim3(32, 8)>>>(
            v, vth, vtl);
    }

    // Causal GQA attention (mma.sync bf16, 3xBF16)
    flash_mma_kernel<<<dim3(SEQ/128, NH, BATCH), 256, FLASH_SMEM>>>(
        qh, ql, kh, kl, vth, vtl, attn);

    // Output projection (mma.sync tf32, 3xTF32)
    gemm_mma_kernel<<<dim3(2048/128, NTOK/128), 256>>>(
        attn, wth + WT_OFF_O, wtl + WT_OFF_O, out, 2048);
}

// round 7
// speedup vs baseline: 3.7973x; 1.7310x over previous
#include <cuda_runtime.h>
#include <cuda_bf16.h>
#include <math.h>

// Problem constants (fixed shapes)
#define HSZ   2048
#define NH    16
#define NKV   4
#define HD    128
#define BATCH 2
#define SEQ   2048
#define NTOK  (BATCH*SEQ)          // 4096

typedef unsigned int u32;
typedef __nv_bfloat16 bf16;

// Scratch (device globals; allocation is forbidden)
__device__ float g_q[(size_t)NTOK*NH*HD];
__device__ float g_k[(size_t)NTOK*NKV*HD];
__device__ float g_v[(size_t)NTOK*NKV*HD];
// bf16 hi/lo split weights (transposed [N][K])
#define WT_TOTAL 10485760
#define WT_OFF_Q 0
#define WT_OFF_K 4194304
#define WT_OFF_V 5242880
#define WT_OFF_O 6291456
__device__ bf16 g_wtbh[(size_t)WT_TOTAL];
__device__ bf16 g_wtbl[(size_t)WT_TOTAL];
// bf16 hi/lo activations
__device__ bf16 g_hsh[(size_t)NTOK*HSZ],  g_hsl[(size_t)NTOK*HSZ];
__device__ bf16 g_attnh[(size_t)NTOK*NH*HD], g_attnl[(size_t)NTOK*NH*HD];
// bf16 hi/lo attention operands
__device__ bf16 g_qh[(size_t)NTOK*NH*HD],  g_ql[(size_t)NTOK*NH*HD];
__device__ bf16 g_kh[(size_t)NTOK*NKV*HD], g_kl[(size_t)NTOK*NKV*HD];
__device__ bf16 g_vth[(size_t)BATCH*NKV*HD*SEQ], g_vtl[(size_t)BATCH*NKV*HD*SEQ];

// ---------------------------------------------------------------------------
// Helpers
// ---------------------------------------------------------------------------
__device__ __forceinline__ void mma_bf16(float* d, const u32* a, u32 b0, u32 b1) {
    asm volatile(
        "mma.sync.aligned.m16n8k16.row.col.f32.bf16.bf16.f32 "
        "{%0,%1,%2,%3}, {%4,%5,%6,%7}, {%8,%9}, {%0,%1,%2,%3};"
        : "+f"(d[0]), "+f"(d[1]), "+f"(d[2]), "+f"(d[3])
        : "r"(a[0]), "r"(a[1]), "r"(a[2]), "r"(a[3]), "r"(b0), "r"(b1));
}

__device__ __forceinline__ u32 pack_bf16(float a, float b) {
    u32 lo = (u32)__bfloat16_as_ushort(__float2bfloat16_rn(a));
    u32 hi = (u32)__bfloat16_as_ushort(__float2bfloat16_rn(b));
    return lo | (hi << 16);
}

__device__ __forceinline__ void cp_async16(u32 dst, const void* src) {
    asm volatile("cp.async.cg.shared.global [%0], [%1], 16;"
                 :: "r"(dst), "l"(src));
}
__device__ __forceinline__ void cp_commit() {
    asm volatile("cp.async.commit_group;");
}
template <int N>
__device__ __forceinline__ void cp_wait() {
    asm volatile("cp.async.wait_group %0;" :: "n"(N));
}

__device__ __forceinline__ u32 smem_u32(const void* p) {
    u32 a;
    asm("{ .reg .u64 t; cvta.to.shared.u64 t, %1; cvt.u32.u64 %0, t; }"
        : "=r"(a) : "l"(p));
    return a;
}

// ---------------------------------------------------------------------------
// Weight transpose + bf16 hi/lo split: W[K][N] -> Th[N][K], Tl[N][K] (bf16)
// block (32,8), grid (N/32, K/32)
// ---------------------------------------------------------------------------
__global__ void transpose_split_kernel(const float* __restrict__ W,
                                       bf16* __restrict__ Th,
                                       bf16* __restrict__ Tl,
                                       int K, int N)
{
    __shared__ float t[32][33];
    const int bx = blockIdx.x * 32;
    const int by = blockIdx.y * 32;
    const int tx = threadIdx.x, ty = threadIdx.y;
#pragma unroll
    for (int j = 0; j < 4; j++)
        t[ty + j * 8][tx] = W[(size_t)(by + ty + j * 8) * N + bx + tx];
    __syncthreads();
#pragma unroll
    for (int j = 0; j < 4; j++) {
        float v = t[tx][ty + j * 8];
        bf16 h = __float2bfloat16_rn(v);
        size_t o = (size_t)(bx + ty + j * 8) * K + by + tx;
        Th[o] = h;
        Tl[o] = __float2bfloat16_rn(v - __bfloat162float(h));
    }
}

// ---------------------------------------------------------------------------
// Activation bf16 hi/lo split (elementwise, vectorized x4)
// ---------------------------------------------------------------------------
__global__ void split_act_kernel(const float* __restrict__ x,
                                 bf16* __restrict__ xh, bf16* __restrict__ xl,
                                 int total4)
{
    int i = blockIdx.x * blockDim.x + threadIdx.x;
    if (i >= total4) return;
    float4 v = *(const float4*)&x[(size_t)i * 4];
    float hx = __bfloat162float(__float2bfloat16_rn(v.x));
    float hy = __bfloat162float(__float2bfloat16_rn(v.y));
    float hz = __bfloat162float(__float2bfloat16_rn(v.z));
    float hw = __bfloat162float(__float2bfloat16_rn(v.w));
    u32* ph = (u32*)&xh[(size_t)i * 4];
    u32* pl = (u32*)&xl[(size_t)i * 4];
    ph[0] = pack_bf16(hx, hy);
    ph[1] = pack_bf16(hz, hw);
    pl[0] = pack_bf16(v.x - hx, v.y - hy);
    pl[1] = pack_bf16(v.z - hz, v.w - hw);
}

// ---------------------------------------------------------------------------
// bf16 GEMM (3xBF16, cp.async double-buffered):
//   C[M,N] = (Ah+Al)[M,2048] @ (Bh+Bl)[N,2048]^T   (all operands bf16 hi/lo)
// CTA tile 128x128, BK=32, 256 threads (8 warps: 4 along M x 2 along N).
// smem rows padded to 40 bf16 (80B) -> conflict-free b32 fragment loads.
// ---------------------------------------------------------------------------
#define GK 2048
#define NCH 64            // 2048/32
#define ROWB 80           // bytes per smem row
#define ARRB 10240        // bytes per array (128*80)
#define STGB 40960        // bytes per stage (4 arrays)
#define GEMM_SMEM (2*STGB)  // 81920

__global__ void __launch_bounds__(256) gemm_bf16_kernel(
    const bf16* __restrict__ Ah, const bf16* __restrict__ Al,
    const bf16* __restrict__ Bh, const bf16* __restrict__ Bl,
    float* __restrict__ C, int N)
{
    extern __shared__ char sm[];
    const u32 smb   = smem_u32(sm);
    const int tid   = threadIdx.x;
    const int lane  = tid & 31;
    const int wid   = tid >> 5;
    const int wm    = wid >> 1;
    const int wn    = wid & 1;
    const int g     = lane >> 2;
    const int t4    = lane & 3;
    const int m0    = blockIdx.y * 128;
    const int n0    = blockIdx.x * 128;

    // Per-thread load slots (8 x 16B per stage)
    const bf16* lsrc[8];
    u32 ldst[8];
#pragma unroll
    for (int i = 0; i < 8; i++) {
        int e   = i * 256 + tid;        // 0..2047
        int arr = e >> 9;               // 0:Ah 1:Al 2:Bh 3:Bl
        int r   = (e >> 2) & 127;
        int ch  = e & 3;
        const bf16* base = (arr == 0) ? Ah : (arr == 1) ? Al : (arr == 2) ? Bh : Bl;
        int row0 = (arr < 2) ? m0 : n0;
        lsrc[i]  = base + (size_t)(row0 + r) * GK + ch * 8;
        ldst[i]  = smb + arr * ARRB + r * ROWB + ch * 16;
    }

    float acc[2][8][4];
#pragma unroll
    for (int mt = 0; mt < 2; mt++)
#pragma unroll
        for (int nt = 0; nt < 8; nt++)
#pragma unroll
            for (int r = 0; r < 4; r++) acc[mt][nt][r] = 0.0f;

    // Prologue: stage 0
#pragma unroll
    for (int i = 0; i < 8; i++) cp_async16(ldst[i], lsrc[i]);
    cp_commit();

    for (int c = 0; c < NCH; c++) {
        if (c + 1 < NCH) {
            const u32 sb = ((c + 1) & 1) * STGB;
            const int koff = (c + 1) * 32;
#pragma unroll
            for (int i = 0; i < 8; i++)
                cp_async16(ldst[i] + sb, lsrc[i] + koff);
            cp_commit();
            cp_wait<1>();
        } else {
            cp_wait<0>();
        }
        __syncthreads();

        const bf16* st = (const bf16*)(sm + (c & 1) * STGB);
        const bf16* sAh = st;
        const bf16* sAl = st + ARRB / 2;
        const bf16* sBh = st + ARRB;          // in bf16 units: ARRB/2 *2
        const bf16* sBl = st + 3 * (ARRB / 2);

#pragma unroll
        for (int step = 0; step < 2; step++) {
            const int kb = step * 16;
            u32 ah[2][4], al[2][4];
#pragma unroll
            for (int mt = 0; mt < 2; mt++) {
                int r = wm * 32 + mt * 16 + g;
                ah[mt][0] = *(const u32*)&sAh[r * 40 + kb + t4 * 2];
                ah[mt][1] = *(const u32*)&sAh[(r + 8) * 40 + kb + t4 * 2];
                ah[mt][2] = *(const u32*)&sAh[r * 40 + kb + 8 + t4 * 2];
                ah[mt][3] = *(const u32*)&sAh[(r + 8) * 40 + kb + 8 + t4 * 2];
                al[mt][0] = *(const u32*)&sAl[r * 40 + kb + t4 * 2];
                al[mt][1] = *(const u32*)&sAl[(r + 8) * 40 + kb + t4 * 2];
                al[mt][2] = *(const u32*)&sAl[r * 40 + kb + 8 + t4 * 2];
                al[mt][3] = *(const u32*)&sAl[(r + 8) * 40 + kb + 8 + t4 * 2];
            }
#pragma unroll
            for (int nt = 0; nt < 8; nt++) {
                int n = wn * 64 + nt * 8 + g;
                u32 bh0 = *(const u32*)&sBh[n * 40 + kb + t4 * 2];
                u32 bh1 = *(const u32*)&sBh[n * 40 + kb + 8 + t4 * 2];
                u32 bl0 = *(const u32*)&sBl[n * 40 + kb + t4 * 2];
                u32 bl1 = *(const u32*)&sBl[n * 40 + kb + 8 + t4 * 2];
#pragma unroll
                for (int mt = 0; mt < 2; mt++) {
                    mma_bf16(acc[mt][nt], ah[mt], bh0, bh1);
                    mma_bf16(acc[mt][nt], ah[mt], bl0, bl1);
                    mma_bf16(acc[mt][nt], al[mt], bh0, bh1);
                }
            }
        }
        __syncthreads();
    }

    // Epilogue
#pragma unroll
    for (int mt = 0; mt < 2; mt++) {
#pragma unroll
        for (int nt = 0; nt < 8; nt++) {
            int r  = m0 + wm * 32 + mt * 16 + g;
            int cb = n0 + wn * 64 + nt * 8 + t4 * 2;
            float2 lo = {acc[mt][nt][0], acc[mt][nt][1]};
            float2 hi = {acc[mt][nt][2], acc[mt][nt][3]};
            *(float2*)&C[(size_t)r * N + cb]       = lo;
            *(float2*)&C[(size_t)(r + 8) * N + cb] = hi;
        }
    }
}

// ---------------------------------------------------------------------------
// RoPE + bf16 hi/lo split. Reads fp32 x [tok][head][HD], writes xh/xl bf16.
// ---------------------------------------------------------------------------
__global__ void rope_split_kernel(const float* __restrict__ x,
                                  bf16* __restrict__ xh, bf16* __restrict__ xl,
                                  const int* __restrict__ pos_ids,
                                  int nheads, int total, float outscale)
{
    int idx = blockIdx.x * blockDim.x + threadIdx.x;
    if (idx >= total) return;
    int j = idx & 63;
    int t = idx >> 6;
    int tok = t / nheads;

    int pos = pos_ids[tok];

    float invf = (float)exp(-(double)j * (9.210340371976184 / 64.0));
    float angf = (float)pos * invf;
    double r = remainder((double)angf, 6.283185307179586);
    float c, s;
    sincosf((float)r, &s, &c);

    const float* base = x + (size_t)t * HD;
    float x1 = base[j];
    float x2 = base[j + 64];
    float o1 = (x1 * c - x2 * s) * outscale;
    float o2 = (x2 * c + x1 * s) * outscale;

    size_t o = (size_t)t * HD;
    bf16 h1 = __float2bfloat16_rn(o1);
    bf16 h2 = __float2bfloat16_rn(o2);
    xh[o + j]      = h1;
    xh[o + j + 64] = h2;
    xl[o + j]      = __float2bfloat16_rn(o1 - __bfloat162float(h1));
    xl[o + j + 64] = __float2bfloat16_rn(o2 - __bfloat162float(h2));
}

// ---------------------------------------------------------------------------
// V transpose + bf16 split: V[(b,s),hk,d] -> Vt[(b,hk),d,s] hi/lo bf16
// ---------------------------------------------------------------------------
__global__ void vt_split_kernel(const float* __restrict__ V,
                                bf16* __restrict__ Vth, bf16* __restrict__ Vtl)
{
    __shared__ float t[32][33];
    const int b  = blockIdx.z >> 2;
    const int hk = blockIdx.z & 3;
    const int s0 = blockIdx.x * 32;
    const int d0 = blockIdx.y * 32;
    const int tx = threadIdx.x, ty = threadIdx.y;
#pragma unroll
    for (int j = 0; j < 4; j++)
        t[ty + j * 8][tx] =
            V[((size_t)(b * SEQ + s0 + ty + j * 8) * NKV + hk) * HD + d0 + tx];
    __syncthreads();
#pragma unroll
    for (int j = 0; j < 4; j++) {
        float v = t[tx][ty + j * 8];
        bf16 h = __float2bfloat16_rn(v);
        size_t o = ((size_t)(b * NKV + hk) * HD + d0 + ty + j * 8) * SEQ + s0 + tx;
        Vth[o] = h;
        Vtl[o] = __float2bfloat16_rn(v - __bfloat162float(h));
    }
}

// ---------------------------------------------------------------------------
// Flash attention with mma.sync bf16 (3xBF16). Causal, GQA.
// Epilogue writes bf16 hi/lo (feeds Wo GEMM directly).
// ---------------------------------------------------------------------------
#define KSTR 136
#define VSTR 72
#define SK_H 0
#define SK_L (64*KSTR)
#define SV_H (2*64*KSTR)
#define SV_L (2*64*KSTR + 128*VSTR)
#define FLASH_SMEM ((2*64*KSTR + 2*128*VSTR) * 2)   // 71680 bytes

__global__ void __launch_bounds__(256, 1) flash_mma_kernel(
    const bf16* __restrict__ Qh, const bf16* __restrict__ Ql,
    const bf16* __restrict__ Kh, const bf16* __restrict__ Kl,
    const bf16* __restrict__ Vth, const bf16* __restrict__ Vtl,
    bf16* __restrict__ Oh, bf16* __restrict__ Ol)
{
    extern __shared__ bf16 smf[];
    const int qt  = blockIdx.x;
    const int h   = blockIdx.y;
    const int b   = blockIdx.z;
    const int hk  = h >> 2;
    const int tid = threadIdx.x;
    const int wid = tid >> 5;
    const int lane = tid & 31;
    const int g   = lane >> 2;
    const int t4  = lane & 3;
    const int q0  = qt * 128;

    const int r0 = q0 + wid * 16 + g;
    const int r1 = r0 + 8;

    u32 qfh[8][4], qfl[8][4];
    {
        const size_t b0 = ((size_t)(b * SEQ + r0) * NH + h) * HD;
        const size_t b1 = ((size_t)(b * SEQ + r1) * NH + h) * HD;
#pragma unroll
        for (int s = 0; s < 8; s++) {
            int d0 = s * 16 + t4 * 2, d1 = d0 + 8;
            qfh[s][0] = *(const u32*)&Qh[b0 + d0];
            qfh[s][1] = *(const u32*)&Qh[b1 + d0];
            qfh[s][2] = *(const u32*)&Qh[b0 + d1];
            qfh[s][3] = *(const u32*)&Qh[b1 + d1];
            qfl[s][0] = *(const u32*)&Ql[b0 + d0];
            qfl[s][1] = *(const u32*)&Ql[b1 + d0];
            qfl[s][2] = *(const u32*)&Ql[b0 + d1];
            qfl[s][3] = *(const u32*)&Ql[b1 + d1];
        }
    }

    float oacc[16][4];
#pragma unroll
    for (int nt = 0; nt < 16; nt++)
#pragma unroll
        for (int r = 0; r < 4; r++) oacc[nt][r] = 0.0f;
    float m0 = -1e30f, m1 = -1e30f, l0 = 0.0f, l1 = 0.0f;

    const int nkt = 2 * qt + 2;

    for (int kt = 0; kt < nkt; kt++) {
        const int k0 = kt * 64;

        {
            const size_t kb = ((size_t)(b * SEQ + k0) * NKV + hk) * HD;
#pragma unroll
            for (int i = 0; i < 8; i++) {
                int e  = i * 256 + tid;
                int hl = e >> 10;
                int r  = (e >> 4) & 63;
                int c4 = e & 15;
                const bf16* src = hl ? Kl : Kh;
                bf16* dst = smf + (hl ? SK_L : SK_H);
                *(float4*)&dst[r * KSTR + c4 * 8] =
                    *(const float4*)&src[kb + (size_t)r * (NKV * HD) + c4 * 8];
            }
        }
        {
            const size_t vb = ((size_t)(b * NKV + hk) * HD) * SEQ + k0;
#pragma unroll
            for (int i = 0; i < 8; i++) {
                int e  = i * 256 + tid;
                int hl = e >> 10;
                int d  = (e >> 3) & 127;
                int c4 = e & 7;
                const bf16* src = hl ? Vtl : Vth;
                bf16* dst = smf + (hl ? SV_L : SV_H);
                *(float4*)&dst[d * VSTR + c4 * 8] =
                    *(const float4*)&src[vb + (size_t)d * SEQ + c4 * 8];
            }
        }
        __syncthreads();

        const bool active = (k0 <= q0 + wid * 16 + 15);
        if (active) {
            float sacc[8][4];
#pragma unroll
            for (int j = 0; j < 8; j++)
#pragma unroll
                for (int r = 0; r < 4; r++) sacc[j][r] = 0.0f;

#pragma unroll
            for (int s = 0; s < 8; s++) {
#pragma unroll
                for (int j = 0; j < 8; j++) {
                    int key = j * 8 + g;
                    u32 bh0 = *(const u32*)&smf[SK_H + key * KSTR + s * 16 + t4 * 2];
                    u32 bh1 = *(const u32*)&smf[SK_H + key * KSTR + s * 16 + 8 + t4 * 2];
                    u32 bl0 = *(const u32*)&smf[SK_L + key * KSTR + s * 16 + t4 * 2];
                    u32 bl1 = *(const u32*)&smf[SK_L + key * KSTR + s * 16 + 8 + t4 * 2];
                    mma_bf16(sacc[j], qfh[s], bh0, bh1);
                    mma_bf16(sacc[j], qfh[s], bl0, bl1);
                    mma_bf16(sacc[j], qfl[s], bh0, bh1);
                }
            }

            if (k0 + 63 > q0) {
#pragma unroll
                for (int j = 0; j < 8; j++) {
                    int c0 = k0 + j * 8 + t4 * 2;
                    if (c0     > r0) sacc[j][0] = -1e30f;
                    if (c0 + 1 > r0) sacc[j][1] = -1e30f;
                    if (c0     > r1) sacc[j][2] = -1e30f;
                    if (c0 + 1 > r1) sacc[j][3] = -1e30f;
                }
            }

            float rm0 = -1e30f, rm1 = -1e30f;
#pragma unroll
            for (int j = 0; j < 8; j++) {
                rm0 = fmaxf(rm0, fmaxf(sacc[j][0], sacc[j][1]));
                rm1 = fmaxf(rm1, fmaxf(sacc[j][2], sacc[j][3]));
            }
            rm0 = fmaxf(rm0, __shfl_xor_sync(0xffffffffu, rm0, 1));
            rm0 = fmaxf(rm0, __shfl_xor_sync(0xffffffffu, rm0, 2));
            rm1 = fmaxf(rm1, __shfl_xor_sync(0xffffffffu, rm1, 1));
            rm1 = fmaxf(rm1, __shfl_xor_sync(0xffffffffu, rm1, 2));
            float mn0 = fmaxf(m0, rm0), mn1 = fmaxf(m1, rm1);
            float a0 = __expf(m0 - mn0), a1 = __expf(m1 - mn1);
            m0 = mn0; m1 = mn1;
            float rs0 = 0.0f, rs1 = 0.0f;
#pragma unroll
            for (int j = 0; j < 8; j++) {
                sacc[j][0] = __expf(sacc[j][0] - m0);
                sacc[j][1] = __expf(sacc[j][1] - m0);
                sacc[j][2] = __expf(sacc[j][2] - m1);
                sacc[j][3] = __expf(sacc[j][3] - m1);
                rs0 += sacc[j][0] + sacc[j][1];
                rs1 += sacc[j][2] + sacc[j][3];
            }
            rs0 += __shfl_xor_sync(0xffffffffu, rs0, 1);
            rs0 += __shfl_xor_sync(0xffffffffu, rs0, 2);
            rs1 += __shfl_xor_sync(0xffffffffu, rs1, 1);
            rs1 += __shfl_xor_sync(0xffffffffu, rs1, 2);
            l0 = l0 * a0 + rs0;
            l1 = l1 * a1 + rs1;
#pragma unroll
            for (int nt = 0; nt < 16; nt++) {
                oacc[nt][0] *= a0; oacc[nt][1] *= a0;
                oacc[nt][2] *= a1; oacc[nt][3] *= a1;
            }

            u32 pfh[4][4], pfl[4][4];
#pragma unroll
            for (int s = 0; s < 4; s++) {
                int j0 = 2 * s, j1 = 2 * s + 1;
                float h00, h01, h10, h11, h20, h21, h30, h31;
                h00 = __bfloat162float(__float2bfloat16_rn(sacc[j0][0]));
                h01 = __bfloat162float(__float2bfloat16_rn(sacc[j0][1]));
                h10 = __bfloat162float(__float2bfloat16_rn(sacc[j0][2]));
                h11 = __bfloat162float(__float2bfloat16_rn(sacc[j0][3]));
                h20 = __bfloat162float(__float2bfloat16_rn(sacc[j1][0]));
                h21 = __bfloat162float(__float2bfloat16_rn(sacc[j1][1]));
                h30 = __bfloat162float(__float2bfloat16_rn(sacc[j1][2]));
                h31 = __bfloat162float(__float2bfloat16_rn(sacc[j1][3]));
                pfh[s][0] = pack_bf16(h00, h01);
                pfh[s][1] = pack_bf16(h10, h11);
                pfh[s][2] = pack_bf16(h20, h21);
                pfh[s][3] = pack_bf16(h30, h31);
                pfl[s][0] = pack_bf16(sacc[j0][0] - h00, sacc[j0][1] - h01);
                pfl[s][1] = pack_bf16(sacc[j0][2] - h10, sacc[j0][3] - h11);
                pfl[s][2] = pack_bf16(sacc[j1][0] - h20, sacc[j1][1] - h21);
                pfl[s][3] = pack_bf16(sacc[j1][2] - h30, sacc[j1][3] - h31);
            }

#pragma unroll
            for (int s = 0; s < 4; s++) {
#pragma unroll
                for (int nt = 0; nt < 16; nt++) {
                    int d = nt * 8 + g;
                    u32 vh0 = *(const u32*)&smf[SV_H + d * VSTR + s * 16 + t4 * 2];
                    u32 vh1 = *(const u32*)&smf[SV_H + d * VSTR + s * 16 + 8 + t4 * 2];
                    u32 vl0 = *(const u32*)&smf[SV_L + d * VSTR + s * 16 + t4 * 2];
                    u32 vl1 = *(const u32*)&smf[SV_L + d * VSTR + s * 16 + 8 + t4 * 2];
                    mma_bf16(oacc[nt], pfh[s], vh0, vh1);
                    mma_bf16(oacc[nt], pfh[s], vl0, vl1);
                    mma_bf16(oacc[nt], pfl[s], vh0, vh1);
                }
            }
        }
        __syncthreads();
    }

    // ---- epilogue: write bf16 hi/lo (feeds Wo GEMM) ----
    float il0 = 1.0f / l0, il1 = 1.0f / l1;
    const size_t ob0 = ((size_t)(b * SEQ + r0) * NH + h) * HD;
    const size_t ob1 = ((size_t)(b * SEQ + r1) * NH + h) * HD;
#pragma unroll
    for (int nt = 0; nt < 16; nt++) {
        int cb = nt * 8 + t4 * 2;
        float o00 = oacc[nt][0] * il0, o01 = oacc[nt][1] * il0;
        float o10 = oacc[nt][2] * il1, o11 = oacc[nt][3] * il1;
        float h00 = __bfloat162float(__float2bfloat16_rn(o00));
        float h01 = __bfloat162float(__float2bfloat16_rn(o01));
        float h10 = __bfloat162float(__float2bfloat16_rn(o10));
        float h11 = __bfloat162float(__float2bfloat16_rn(o11));
        *(u32*)&Oh[ob0 + cb] = pack_bf16(h00, h01);
        *(u32*)&Oh[ob1 + cb] = pack_bf16(h10, h11);
        *(u32*)&Ol[ob0 + cb] = pack_bf16(o00 - h00, o01 - h01);
        *(u32*)&Ol[ob1 + cb] = pack_bf16(o10 - h10, o11 - h11);
    }
}

// ---------------------------------------------------------------------------
// Launch
// ---------------------------------------------------------------------------
extern "C" void kernel_launch(void* const* d_in, const int* in_sizes, int n_in,
                              void* d_out, int out_size)
{
    const float* hs  = (const float*)d_in[0];
    const int*   pos = (const int*)d_in[1];
    const float* Wq  = (const float*)d_in[2];
    const float* Wk  = (const float*)d_in[3];
    const float* Wv  = (const float*)d_in[4];
    const float* Wo  = (const float*)d_in[5];
    float*       out = (float*)d_out;

    float *q, *k, *v;
    bf16 *wtbh, *wtbl, *hsh, *hsl, *attnh, *attnl;
    bf16 *qh, *ql, *kh, *kl, *vth, *vtl;
    cudaGetSymbolAddress((void**)&q,     g_q);
    cudaGetSymbolAddress((void**)&k,     g_k);
    cudaGetSymbolAddress((void**)&v,     g_v);
    cudaGetSymbolAddress((void**)&wtbh,  g_wtbh);
    cudaGetSymbolAddress((void**)&wtbl,  g_wtbl);
    cudaGetSymbolAddress((void**)&hsh,   g_hsh);
    cudaGetSymbolAddress((void**)&hsl,   g_hsl);
    cudaGetSymbolAddress((void**)&attnh, g_attnh);
    cudaGetSymbolAddress((void**)&attnl, g_attnl);
    cudaGetSymbolAddress((void**)&qh,    g_qh);
    cudaGetSymbolAddress((void**)&ql,    g_ql);
    cudaGetSymbolAddress((void**)&kh,    g_kh);
    cudaGetSymbolAddress((void**)&kl,    g_kl);
    cudaGetSymbolAddress((void**)&vth,   g_vth);
    cudaGetSymbolAddress((void**)&vtl,   g_vtl);

    cudaFuncSetAttribute(flash_mma_kernel,
                         cudaFuncAttributeMaxDynamicSharedMemorySize, FLASH_SMEM);
    cudaFuncSetAttribute(gemm_bf16_kernel,
                         cudaFuncAttributeMaxDynamicSharedMemorySize, GEMM_SMEM);

    // Weight transpose + bf16 split
    transpose_split_kernel<<<dim3(2048/32, 2048/32), dim3(32, 8)>>>(
        Wq, wtbh + WT_OFF_Q, wtbl + WT_OFF_Q, HSZ, 2048);
    transpose_split_kernel<<<dim3(512/32, 2048/32), dim3(32, 8)>>>(
        Wk, wtbh + WT_OFF_K, wtbl + WT_OFF_K, HSZ, 512);
    transpose_split_kernel<<<dim3(512/32, 2048/32), dim3(32, 8)>>>(
        Wv, wtbh + WT_OFF_V, wtbl + WT_OFF_V, HSZ, 512);
    transpose_split_kernel<<<dim3(2048/32, 2048/32), dim3(32, 8)>>>(
        Wo, wtbh + WT_OFF_O, wtbl + WT_OFF_O, HSZ, 2048);

    // hidden_states bf16 split
    split_act_kernel<<<(NTOK * HSZ / 4 + 255) / 256, 256>>>(
        hs, hsh, hsl, NTOK * HSZ / 4);

    // QKV projections (3xBF16 cp.async GEMM)
    gemm_bf16_kernel<<<dim3(2048/128, NTOK/128), 256, GEMM_SMEM>>>(
        hsh, hsl, wtbh + WT_OFF_Q, wtbl + WT_OFF_Q, q, 2048);
    gemm_bf16_kernel<<<dim3(512/128, NTOK/128), 256, GEMM_SMEM>>>(
        hsh, hsl, wtbh + WT_OFF_K, wtbl + WT_OFF_K, k, 512);
    gemm_bf16_kernel<<<dim3(512/128, NTOK/128), 256, GEMM_SMEM>>>(
        hsh, hsl, wtbh + WT_OFF_V, wtbl + WT_OFF_V, v, 512);

    // RoPE + bf16 split; V transpose+split
    {
        int total_q = NTOK * NH * 64;
        int total_k = NTOK * NKV * 64;
        rope_split_kernel<<<(total_q + 255) / 256, 256>>>(
            q, qh, ql, pos, NH, total_q, 0.08838834764831845f);
        rope_split_kernel<<<(total_k + 255) / 256, 256>>>(
            k, kh, kl, pos, NKV, total_k, 1.0f);
        vt_split_kernel<<<dim3(SEQ/32, HD/32, BATCH*NKV), dim3(32, 8)>>>(
            v, vth, vtl);
    }

    // Causal GQA attention (3xBF16); writes bf16 hi/lo attn
    flash_mma_kernel<<<dim3(SEQ/128, NH, BATCH), 256, FLASH_SMEM>>>(
        qh, ql, kh, kl, vth, vtl, attnh, attnl);

    // Output projection (3xBF16 cp.async GEMM)
    gemm_bf16_kernel<<<dim3(2048/128, NTOK/128), 256, GEMM_SMEM>>>(
        attnh, attnl, wtbh + WT_OFF_O, wtbl + WT_OFF_O, out, 2048);
}